// round 3
// baseline (speedup 1.0000x reference)
#include <cuda_runtime.h>
#include <math.h>
#include <stdint.h>

#define NN    30000
#define DMAXN 16
#define INF   128
#define HIDF  256

// ---------------- scratch (device globals; no allocations allowed) ----------
__device__ float d_h1[2][NN * INF];     // LSTM1 hidden ping-pong (sorted-row indexed)
__device__ float d_c1[NN * INF];        // LSTM1 cell state
__device__ float d_hout[NN * HIDF];     // layer-1 output (node indexed)
__device__ float d_h2[2][NN * HIDF];    // LSTM2 hidden ping-pong
__device__ float d_c2[NN * HIDF];       // LSTM2 cell state
__device__ int   d_perm[NN];            // sorted row -> node
__device__ int   d_rank[NN];            // node -> sorted row
__device__ int   d_cnt[DMAXN + 2];
__device__ int   d_ofs[DMAXN + 2];
__device__ int   d_Kt[DMAXN + 1];       // K_t = #nodes with deg > t

// ---------------- counting sort by degree (descending) ----------------------
__global__ void sort_zero_k() {
    if (threadIdx.x < DMAXN + 2) d_cnt[threadIdx.x] = 0;
}

__global__ void sort_hist_k(const int* __restrict__ deg, int n) {
    int i = blockIdx.x * blockDim.x + threadIdx.x;
    if (i < n) atomicAdd(&d_cnt[deg[i]], 1);
}

__global__ void sort_scan_k() {
    // single thread: tiny
    int ofs[DMAXN + 2];
    int run = 0;
    for (int d = DMAXN; d >= 1; --d) { ofs[d] = run; run += d_cnt[d]; }
    for (int d = 1; d <= DMAXN; ++d) d_ofs[d] = ofs[d];
    for (int t = 0; t < DMAXN; ++t) d_Kt[t] = ofs[t + 1] + d_cnt[t + 1];
}

__global__ void sort_scatter_k(const int* __restrict__ deg, int n) {
    int i = blockIdx.x * blockDim.x + threadIdx.x;
    if (i < n) {
        int p = atomicAdd(&d_ofs[deg[i]], 1);
        d_perm[p] = i;
        d_rank[i] = p;
    }
}

// ---------------- state zero-init --------------------------------------------
__global__ void zero_states_k() {
    const int n1 = NN * INF / 4;
    const int n2 = NN * HIDF / 4;
    float4 z = make_float4(0.f, 0.f, 0.f, 0.f);
    int stride = gridDim.x * blockDim.x;
    for (int i = blockIdx.x * blockDim.x + threadIdx.x; i < n2; i += stride) {
        reinterpret_cast<float4*>(d_h2[0])[i] = z;
        reinterpret_cast<float4*>(d_c2)[i]    = z;
        if (i < n1) {
            reinterpret_cast<float4*>(d_h1[0])[i] = z;
            reinterpret_cast<float4*>(d_c1)[i]    = z;
        }
    }
}

// ---------------- fused LSTM step: gates GEMM + cell -------------------------
// Block tile: 64 rows x 32 cell-cols (=128 gate cols across i/f/g/o groups).
// K = 2H (gathered x | previous h). 128 threads, 4x(4x4) register micro-tiles.
template <int H, int LAYER>
__global__ __launch_bounds__(128, 3)
void lstm_step_k(const float* __restrict__ feat,
                 const int*   __restrict__ nbr_idx,
                 const float* __restrict__ Wih,  // [4H, H]
                 const float* __restrict__ Whh,  // [4H, H]
                 const float* __restrict__ bih,
                 const float* __restrict__ bhh,
                 int t, int n)
{
    const int Kt = d_Kt[t];
    const int r0 = blockIdx.x * 64;
    if (r0 >= Kt) return;
    const int j0 = blockIdx.y * 32;

    constexpr int NCH = (2 * H) / 16;

    __shared__ __align__(16) float As[2][16][64];
    __shared__ __align__(16) float Ws[2][16][128];

    const float* src    = (LAYER == 1) ? feat : d_hout;
    const float* hread  = (LAYER == 1) ? d_h1[t & 1] : d_h2[t & 1];
    float*       hwrite = (LAYER == 1) ? d_h1[(t + 1) & 1] : d_h2[(t + 1) & 1];
    float*       cst    = (LAYER == 1) ? d_c1 : d_c2;

    const int tid    = threadIdx.x;
    const int la_row = tid & 63;
    const int la_seg = tid >> 6;

    // A-tile source pointers (gathered x for k<H, previous h for k>=H)
    int ar = r0 + la_row;
    if (ar > n - 1) ar = n - 1;
    const int node = d_perm[ar];
    const int nbr  = nbr_idx[node * DMAXN + t];
    const float* xptr = src + (size_t)nbr * H + la_seg * 8;
    const float* hptr = hread + (size_t)ar * H + la_seg * 8;

    // W-tile source pointers: this thread's gate row
    const int qg = tid >> 5;              // gate group 0..3
    const int jj = j0 + (tid & 31);       // cell column
    const int g  = qg * H + jj;
    const float* wihp = Wih + (size_t)g * H;
    const float* whhp = Whh + (size_t)g * H;

    const int ty = tid >> 3;  // 0..15 -> rows ty*4..+3
    const int tx = tid & 7;   // 0..7  -> cell cols tx*4..+3

    float acc[4][4][4];
#pragma unroll
    for (int i = 0; i < 4; i++)
#pragma unroll
        for (int q = 0; q < 4; q++)
#pragma unroll
            for (int c = 0; c < 4; c++) acc[i][q][c] = 0.f;

    // prologue: chunk 0 (always x / Wih region)
    float4 na0 = *(const float4*)(xptr);
    float4 na1 = *(const float4*)(xptr + 4);
    float4 nw0 = *(const float4*)(wihp);
    float4 nw1 = *(const float4*)(wihp + 4);
    float4 nw2 = *(const float4*)(wihp + 8);
    float4 nw3 = *(const float4*)(wihp + 12);
    {
        const int kb = la_seg * 8;
        As[0][kb + 0][la_row] = na0.x; As[0][kb + 1][la_row] = na0.y;
        As[0][kb + 2][la_row] = na0.z; As[0][kb + 3][la_row] = na0.w;
        As[0][kb + 4][la_row] = na1.x; As[0][kb + 5][la_row] = na1.y;
        As[0][kb + 6][la_row] = na1.z; As[0][kb + 7][la_row] = na1.w;
        Ws[0][0][tid] = nw0.x;  Ws[0][1][tid] = nw0.y;  Ws[0][2][tid] = nw0.z;  Ws[0][3][tid] = nw0.w;
        Ws[0][4][tid] = nw1.x;  Ws[0][5][tid] = nw1.y;  Ws[0][6][tid] = nw1.z;  Ws[0][7][tid] = nw1.w;
        Ws[0][8][tid] = nw2.x;  Ws[0][9][tid] = nw2.y;  Ws[0][10][tid] = nw2.z; Ws[0][11][tid] = nw2.w;
        Ws[0][12][tid] = nw3.x; Ws[0][13][tid] = nw3.y; Ws[0][14][tid] = nw3.z; Ws[0][15][tid] = nw3.w;
    }

#pragma unroll 1
    for (int c = 0; c < NCH; c++) {
        __syncthreads();
        const int buf = c & 1;
        const bool more = (c + 1 < NCH);
        if (more) {
            int kk = (c + 1) * 16;
            {
                const float* p = (kk < H) ? (xptr + kk) : (hptr + (kk - H));
                na0 = *(const float4*)(p);
                na1 = *(const float4*)(p + 4);
            }
            {
                const float* p = (kk < H) ? (wihp + kk) : (whhp + (kk - H));
                nw0 = *(const float4*)(p);
                nw1 = *(const float4*)(p + 4);
                nw2 = *(const float4*)(p + 8);
                nw3 = *(const float4*)(p + 12);
            }
        }
#pragma unroll
        for (int k = 0; k < 16; k++) {
            const float4 av = *(const float4*)(&As[buf][k][ty * 4]);
            const float4 b0 = *(const float4*)(&Ws[buf][k][tx * 4]);
            const float4 b1 = *(const float4*)(&Ws[buf][k][32 + tx * 4]);
            const float4 b2 = *(const float4*)(&Ws[buf][k][64 + tx * 4]);
            const float4 b3 = *(const float4*)(&Ws[buf][k][96 + tx * 4]);
            const float a4[4] = {av.x, av.y, av.z, av.w};
            const float b4[4][4] = {{b0.x, b0.y, b0.z, b0.w},
                                    {b1.x, b1.y, b1.z, b1.w},
                                    {b2.x, b2.y, b2.z, b2.w},
                                    {b3.x, b3.y, b3.z, b3.w}};
#pragma unroll
            for (int i = 0; i < 4; i++)
#pragma unroll
                for (int q = 0; q < 4; q++)
#pragma unroll
                    for (int cc = 0; cc < 4; cc++)
                        acc[i][q][cc] = fmaf(a4[i], b4[q][cc], acc[i][q][cc]);
        }
        if (more) {
            const int nb = (c + 1) & 1;
            const int kb = la_seg * 8;
            As[nb][kb + 0][la_row] = na0.x; As[nb][kb + 1][la_row] = na0.y;
            As[nb][kb + 2][la_row] = na0.z; As[nb][kb + 3][la_row] = na0.w;
            As[nb][kb + 4][la_row] = na1.x; As[nb][kb + 5][la_row] = na1.y;
            As[nb][kb + 6][la_row] = na1.z; As[nb][kb + 7][la_row] = na1.w;
            Ws[nb][0][tid] = nw0.x;  Ws[nb][1][tid] = nw0.y;  Ws[nb][2][tid] = nw0.z;  Ws[nb][3][tid] = nw0.w;
            Ws[nb][4][tid] = nw1.x;  Ws[nb][5][tid] = nw1.y;  Ws[nb][6][tid] = nw1.z;  Ws[nb][7][tid] = nw1.w;
            Ws[nb][8][tid] = nw2.x;  Ws[nb][9][tid] = nw2.y;  Ws[nb][10][tid] = nw2.z; Ws[nb][11][tid] = nw2.w;
            Ws[nb][12][tid] = nw3.x; Ws[nb][13][tid] = nw3.y; Ws[nb][14][tid] = nw3.z; Ws[nb][15][tid] = nw3.w;
        }
    }

    // ---- fused LSTM cell epilogue ----
    float bsum[4][4];
#pragma unroll
    for (int cc = 0; cc < 4; cc++) {
        const int j = j0 + tx * 4 + cc;
#pragma unroll
        for (int q = 0; q < 4; q++)
            bsum[q][cc] = bih[q * H + j] + bhh[q * H + j];
    }
#pragma unroll
    for (int i = 0; i < 4; i++) {
        const int r = r0 + ty * 4 + i;
        if (r >= Kt) continue;
#pragma unroll
        for (int cc = 0; cc < 4; cc++) {
            const int j = j0 + tx * 4 + cc;
            const float gi = acc[i][0][cc] + bsum[0][cc];
            const float gf = acc[i][1][cc] + bsum[1][cc];
            const float gg = acc[i][2][cc] + bsum[2][cc];
            const float go = acc[i][3][cc] + bsum[3][cc];
            const float si = 1.f / (1.f + __expf(-gi));
            const float sf = 1.f / (1.f + __expf(-gf));
            const float so = 1.f / (1.f + __expf(-go));
            const float tg = tanhf(gg);
            const size_t off = (size_t)r * H + j;
            const float cn = sf * cst[off] + si * tg;
            const float hn = so * tanhf(cn);
            cst[off] = cn;
            hwrite[off] = hn;
        }
    }
}

// ---------------- fused FC: out = act(A1 @ W1^T + m @ W2^T + b) --------------
// A1 node-indexed; m gathered from sorted h buffer (parity = deg & 1).
template <int K1, int K2, int NOUT, int LAYER>
__global__ __launch_bounds__(128, 4)
void fc_k(const float* __restrict__ A1in,
          const int*   __restrict__ deg,
          const float* __restrict__ W1,  // [NOUT, K1]
          const float* __restrict__ W2,  // [NOUT, K2]
          const float* __restrict__ bias,
          float* __restrict__ outp,
          int n)
{
    const int r0 = blockIdx.x * 64;
    if (r0 >= n) return;
    const int j0 = blockIdx.y * 64;

    constexpr int NCH = (K1 + K2) / 16;

    __shared__ __align__(16) float As[2][16][64];
    __shared__ __align__(16) float Ws[2][16][64];

    const float* A1 = (LAYER == 1) ? A1in : d_hout;
    float* out      = (LAYER == 1) ? d_hout : outp;

    const int tid    = threadIdx.x;
    const int la_row = tid & 63;
    const int la_seg = tid >> 6;

    int ar = r0 + la_row;
    if (ar > n - 1) ar = n - 1;
    const int rk  = d_rank[ar];
    const int par = deg[ar] & 1;
    const float* hbuf = (LAYER == 1) ? d_h1[par] : d_h2[par];
    const float* p1 = A1 + (size_t)ar * K1 + la_seg * 8;
    const float* p2 = hbuf + (size_t)rk * K2 + la_seg * 8;

    const int lw_col = tid & 63;
    const int lw_seg = tid >> 6;
    const int jrow = j0 + lw_col;
    const float* q1 = W1 + (size_t)jrow * K1 + lw_seg * 8;
    const float* q2 = W2 + (size_t)jrow * K2 + lw_seg * 8;

    const int ty = tid >> 3;  // rows ty*4..+3
    const int tx = tid & 7;   // cols {tx*4..+3} and {32+tx*4..+3}

    float acc[4][2][4];
#pragma unroll
    for (int i = 0; i < 4; i++)
#pragma unroll
        for (int h = 0; h < 2; h++)
#pragma unroll
            for (int c = 0; c < 4; c++) acc[i][h][c] = 0.f;

    // prologue chunk 0 (k < K1 always since K1 >= 16)
    float4 na0 = *(const float4*)(p1);
    float4 na1 = *(const float4*)(p1 + 4);
    float4 nw0 = *(const float4*)(q1);
    float4 nw1 = *(const float4*)(q1 + 4);
    {
        const int kb = la_seg * 8;
        As[0][kb + 0][la_row] = na0.x; As[0][kb + 1][la_row] = na0.y;
        As[0][kb + 2][la_row] = na0.z; As[0][kb + 3][la_row] = na0.w;
        As[0][kb + 4][la_row] = na1.x; As[0][kb + 5][la_row] = na1.y;
        As[0][kb + 6][la_row] = na1.z; As[0][kb + 7][la_row] = na1.w;
        const int kw = lw_seg * 8;
        Ws[0][kw + 0][lw_col] = nw0.x; Ws[0][kw + 1][lw_col] = nw0.y;
        Ws[0][kw + 2][lw_col] = nw0.z; Ws[0][kw + 3][lw_col] = nw0.w;
        Ws[0][kw + 4][lw_col] = nw1.x; Ws[0][kw + 5][lw_col] = nw1.y;
        Ws[0][kw + 6][lw_col] = nw1.z; Ws[0][kw + 7][lw_col] = nw1.w;
    }

#pragma unroll 1
    for (int c = 0; c < NCH; c++) {
        __syncthreads();
        const int buf = c & 1;
        const bool more = (c + 1 < NCH);
        if (more) {
            {
                int kk = (c + 1) * 16 + la_seg * 8;
                const float* p = (kk < K1) ? (p1 - la_seg * 8 + kk)
                                           : (p2 - la_seg * 8 + (kk - K1));
                na0 = *(const float4*)(p);
                na1 = *(const float4*)(p + 4);
            }
            {
                int kk = (c + 1) * 16 + lw_seg * 8;
                const float* p = (kk < K1) ? (q1 - lw_seg * 8 + kk)
                                           : (q2 - lw_seg * 8 + (kk - K1));
                nw0 = *(const float4*)(p);
                nw1 = *(const float4*)(p + 4);
            }
        }
#pragma unroll
        for (int k = 0; k < 16; k++) {
            const float4 av = *(const float4*)(&As[buf][k][ty * 4]);
            const float4 b0 = *(const float4*)(&Ws[buf][k][tx * 4]);
            const float4 b1 = *(const float4*)(&Ws[buf][k][32 + tx * 4]);
            const float a4[4] = {av.x, av.y, av.z, av.w};
            const float b4[2][4] = {{b0.x, b0.y, b0.z, b0.w},
                                    {b1.x, b1.y, b1.z, b1.w}};
#pragma unroll
            for (int i = 0; i < 4; i++)
#pragma unroll
                for (int h = 0; h < 2; h++)
#pragma unroll
                    for (int cc = 0; cc < 4; cc++)
                        acc[i][h][cc] = fmaf(a4[i], b4[h][cc], acc[i][h][cc]);
        }
        if (more) {
            const int nb = (c + 1) & 1;
            const int kb = la_seg * 8;
            As[nb][kb + 0][la_row] = na0.x; As[nb][kb + 1][la_row] = na0.y;
            As[nb][kb + 2][la_row] = na0.z; As[nb][kb + 3][la_row] = na0.w;
            As[nb][kb + 4][la_row] = na1.x; As[nb][kb + 5][la_row] = na1.y;
            As[nb][kb + 6][la_row] = na1.z; As[nb][kb + 7][la_row] = na1.w;
            const int kw = lw_seg * 8;
            Ws[nb][kw + 0][lw_col] = nw0.x; Ws[nb][kw + 1][lw_col] = nw0.y;
            Ws[nb][kw + 2][lw_col] = nw0.z; Ws[nb][kw + 3][lw_col] = nw0.w;
            Ws[nb][kw + 4][lw_col] = nw1.x; Ws[nb][kw + 5][lw_col] = nw1.y;
            Ws[nb][kw + 6][lw_col] = nw1.z; Ws[nb][kw + 7][lw_col] = nw1.w;
        }
    }

#pragma unroll
    for (int i = 0; i < 4; i++) {
        const int r = r0 + ty * 4 + i;
        if (r >= n) continue;
#pragma unroll
        for (int h = 0; h < 2; h++)
#pragma unroll
            for (int cc = 0; cc < 4; cc++) {
                const int j = j0 + h * 32 + tx * 4 + cc;
                float v = acc[i][h][cc] + bias[j];
                if (LAYER == 1) v = fmaxf(v, 0.f);
                out[(size_t)r * NOUT + j] = v;
            }
    }
}

// ---------------- launch ----------------------------------------------------
extern "C" void kernel_launch(void* const* d_in, const int* in_sizes, int n_in,
                              void* d_out, int out_size)
{
    const float* feat    = (const float*)d_in[0];
    const int*   nbr     = (const int*)d_in[1];
    const int*   deg     = (const int*)d_in[2];
    const float* Wih1    = (const float*)d_in[3];
    const float* Whh1    = (const float*)d_in[4];
    const float* bih1    = (const float*)d_in[5];
    const float* bhh1    = (const float*)d_in[6];
    const float* Wself1  = (const float*)d_in[7];
    const float* Wneigh1 = (const float*)d_in[8];
    const float* b1      = (const float*)d_in[9];
    const float* Wih2    = (const float*)d_in[10];
    const float* Whh2    = (const float*)d_in[11];
    const float* bih2    = (const float*)d_in[12];
    const float* bhh2    = (const float*)d_in[13];
    const float* Wself2  = (const float*)d_in[14];
    const float* Wneigh2 = (const float*)d_in[15];
    const float* b2      = (const float*)d_in[16];

    const int n  = in_sizes[2];         // = N (deg element count)
    const int rb = (n + 63) / 64;

    // degree sort (descending) + K_t table
    sort_zero_k<<<1, 32>>>();
    sort_hist_k<<<(n + 255) / 256, 256>>>(deg, n);
    sort_scan_k<<<1, 1>>>();
    sort_scatter_k<<<(n + 255) / 256, 256>>>(deg, n);

    // zero LSTM states
    zero_states_k<<<4096, 256>>>();

    // layer 1: LSTM over neighbors (H=128), 16 steps
    for (int t = 0; t < 16; t++)
        lstm_step_k<128, 1><<<dim3(rb, 4), 128>>>(feat, nbr, Wih1, Whh1,
                                                  bih1, bhh1, t, n);
    // layer 1 FC + relu -> d_hout [N, 256]
    fc_k<128, 128, 256, 1><<<dim3(rb, 4), 128>>>(feat, deg, Wself1, Wneigh1,
                                                 b1, nullptr, n);

    // layer 2: LSTM over neighbors of hout (H=256), 16 steps
    for (int t = 0; t < 16; t++)
        lstm_step_k<256, 2><<<dim3(rb, 8), 128>>>(feat, nbr, Wih2, Whh2,
                                                  bih2, bhh2, t, n);
    // layer 2 FC -> d_out [N, 64]
    fc_k<256, 256, 64, 2><<<dim3(rb, 1), 128>>>(feat, deg, Wself2, Wneigh2,
                                                b2, (float*)d_out, n);
}

// round 6
// speedup vs baseline: 2.0809x; 2.0809x over previous
#include <cuda_runtime.h>
#include <math.h>
#include <stdint.h>

#define NN    30000
#define DMAXN 16
#define INF   128
#define HIDF  256

typedef unsigned long long ull;

// ---------------- f32x2 packed-FMA helpers (Blackwell FFMA2) -----------------
__device__ __forceinline__ void fma2(ull& d, ull a, ull b) {
    asm("fma.rn.f32x2 %0, %1, %2, %0;" : "+l"(d) : "l"(a), "l"(b));
}
__device__ __forceinline__ ull bcast2(float x) {
    ull r; asm("mov.b64 %0, {%1, %1};" : "=l"(r) : "f"(x)); return r;
}
__device__ __forceinline__ float2 unpk(ull v) {
    float2 f; asm("mov.b64 {%0, %1}, %2;" : "=f"(f.x), "=f"(f.y) : "l"(v)); return f;
}

__device__ __forceinline__ float sigmoid_f(float x) {
    float e = __expf(-x);
    return __fdividef(1.f, 1.f + e);
}
__device__ __forceinline__ float tanh_f(float x) {
    float ax = fabsf(x);
    float e = __expf(-2.f * ax);
    float r = __fdividef(1.f - e, 1.f + e);
    return copysignf(r, x);
}

// ---------------- scratch (device globals; no allocations allowed) ----------
__device__ float d_h1[2][NN * INF];     // LSTM1 hidden ping-pong (sorted rows)
__device__ float d_c1[NN * INF];        // LSTM1 cell state (sorted rows)
__device__ float d_hout[NN * HIDF];     // layer-1 output (node indexed)
__device__ float d_h2[2][NN * HIDF];    // LSTM2 hidden ping-pong
__device__ float d_c2[NN * HIDF];       // LSTM2 cell state
__device__ float d_gx1[NN * 4 * INF];   // precomputed x-gates layer1 (node idx)
__device__ float d_gx2[NN * 4 * HIDF];  // precomputed x-gates layer2 (node idx)
__device__ int   d_perm[NN];            // sorted row -> node
__device__ int   d_rank[NN];            // node -> sorted row
__device__ int   d_cnt[DMAXN + 2];
__device__ int   d_ofs[DMAXN + 2];
__device__ int   d_Kt[DMAXN + 1];       // K_t = #nodes with deg > t

// ---------------- counting sort by degree (descending) ----------------------
__global__ void sort_zero_k() {
    if (threadIdx.x < DMAXN + 2) d_cnt[threadIdx.x] = 0;
}

__global__ void sort_hist_k(const int* __restrict__ deg, int n) {
    int i = blockIdx.x * blockDim.x + threadIdx.x;
    if (i < n) atomicAdd(&d_cnt[deg[i]], 1);
}

__global__ void sort_scan_k() {
    int ofs[DMAXN + 2];
    int run = 0;
    for (int d = DMAXN; d >= 1; --d) { ofs[d] = run; run += d_cnt[d]; }
    for (int d = 1; d <= DMAXN; ++d) d_ofs[d] = ofs[d];
    for (int t = 0; t < DMAXN; ++t) d_Kt[t] = ofs[t + 1] + d_cnt[t + 1];
}

__global__ void sort_scatter_k(const int* __restrict__ deg, int n) {
    int i = blockIdx.x * blockDim.x + threadIdx.x;
    if (i < n) {
        int p = atomicAdd(&d_ofs[deg[i]], 1);
        d_perm[p] = i;
        d_rank[i] = p;
    }
}

// ---------------- state zero-init (only c needed; h never read before write)-
__global__ void zero_states_k() {
    const int n1 = NN * INF / 4;
    const int n2 = NN * HIDF / 4;
    float4 z = make_float4(0.f, 0.f, 0.f, 0.f);
    int stride = gridDim.x * blockDim.x;
    for (int i = blockIdx.x * blockDim.x + threadIdx.x; i < n2; i += stride) {
        reinterpret_cast<float4*>(d_c2)[i] = z;
        if (i < n1) reinterpret_cast<float4*>(d_c1)[i] = z;
    }
}

// ---------------- gx = A @ W^T  (A [n,K], W [4K,K], out [n,4K]) --------------
// Block 64 rows x 64 cols, 128 threads, f32x2 micro-kernel 4x(2x4).
template <int K, int SRC>
__global__ __launch_bounds__(128, 3)
void gemm_xw_k(const float* __restrict__ Ain, const float* __restrict__ W, int n)
{
    const int r0 = blockIdx.x * 64;
    if (r0 >= n) return;
    const int j0 = blockIdx.y * 64;
    constexpr int NCH = K / 16;
    constexpr int M = 4 * K;

    __shared__ __align__(16) float As[2][16][64];
    __shared__ __align__(16) float Ws[2][16][64];

    const float* A = (SRC == 1) ? Ain : d_hout;
    float* out     = (SRC == 1) ? d_gx1 : d_gx2;

    const int tid = threadIdx.x;
    const int la_row = tid & 63;
    const int la_seg = tid >> 6;
    int ar = r0 + la_row; if (ar > n - 1) ar = n - 1;
    const float* p = A + (size_t)ar * K;
    const float* q = W + (size_t)(j0 + la_row) * K;

    const int ty = tid >> 3, tx = tid & 7;

    ull acc2[4][2][2];
#pragma unroll
    for (int i = 0; i < 4; i++)
#pragma unroll
        for (int h = 0; h < 2; h++) { acc2[i][h][0] = 0ull; acc2[i][h][1] = 0ull; }

    float4 na0, na1, nw0, nw1;
    {
        const int kk = la_seg * 8;
        na0 = *(const float4*)(p + kk);
        na1 = *(const float4*)(p + kk + 4);
        nw0 = *(const float4*)(q + kk);
        nw1 = *(const float4*)(q + kk + 4);
        As[0][kk + 0][la_row] = na0.x; As[0][kk + 1][la_row] = na0.y;
        As[0][kk + 2][la_row] = na0.z; As[0][kk + 3][la_row] = na0.w;
        As[0][kk + 4][la_row] = na1.x; As[0][kk + 5][la_row] = na1.y;
        As[0][kk + 6][la_row] = na1.z; As[0][kk + 7][la_row] = na1.w;
        Ws[0][kk + 0][la_row] = nw0.x; Ws[0][kk + 1][la_row] = nw0.y;
        Ws[0][kk + 2][la_row] = nw0.z; Ws[0][kk + 3][la_row] = nw0.w;
        Ws[0][kk + 4][la_row] = nw1.x; Ws[0][kk + 5][la_row] = nw1.y;
        Ws[0][kk + 6][la_row] = nw1.z; Ws[0][kk + 7][la_row] = nw1.w;
    }

#pragma unroll 1
    for (int c = 0; c < NCH; c++) {
        __syncthreads();
        const int buf = c & 1;
        const bool more = (c + 1 < NCH);
        if (more) {
            const int kk = (c + 1) * 16 + la_seg * 8;
            na0 = *(const float4*)(p + kk);
            na1 = *(const float4*)(p + kk + 4);
            nw0 = *(const float4*)(q + kk);
            nw1 = *(const float4*)(q + kk + 4);
        }
#pragma unroll
        for (int k = 0; k < 16; k++) {
            const float4 av = *(const float4*)(&As[buf][k][ty * 4]);
            ull a2[4];
            a2[0] = bcast2(av.x); a2[1] = bcast2(av.y);
            a2[2] = bcast2(av.z); a2[3] = bcast2(av.w);
            const ulonglong2 w0 = *(const ulonglong2*)(&Ws[buf][k][tx * 4]);
            const ulonglong2 w1 = *(const ulonglong2*)(&Ws[buf][k][32 + tx * 4]);
#pragma unroll
            for (int i = 0; i < 4; i++) {
                fma2(acc2[i][0][0], a2[i], w0.x); fma2(acc2[i][0][1], a2[i], w0.y);
                fma2(acc2[i][1][0], a2[i], w1.x); fma2(acc2[i][1][1], a2[i], w1.y);
            }
        }
        if (more) {
            const int nb = (c + 1) & 1;
            const int kb = la_seg * 8;
            As[nb][kb + 0][la_row] = na0.x; As[nb][kb + 1][la_row] = na0.y;
            As[nb][kb + 2][la_row] = na0.z; As[nb][kb + 3][la_row] = na0.w;
            As[nb][kb + 4][la_row] = na1.x; As[nb][kb + 5][la_row] = na1.y;
            As[nb][kb + 6][la_row] = na1.z; As[nb][kb + 7][la_row] = na1.w;
            Ws[nb][kb + 0][la_row] = nw0.x; Ws[nb][kb + 1][la_row] = nw0.y;
            Ws[nb][kb + 2][la_row] = nw0.z; Ws[nb][kb + 3][la_row] = nw0.w;
            Ws[nb][kb + 4][la_row] = nw1.x; Ws[nb][kb + 5][la_row] = nw1.y;
            Ws[nb][kb + 6][la_row] = nw1.z; Ws[nb][kb + 7][la_row] = nw1.w;
        }
    }

#pragma unroll
    for (int i = 0; i < 4; i++) {
        const int r = r0 + ty * 4 + i;
        if (r >= n) continue;
#pragma unroll
        for (int h = 0; h < 2; h++) {
            const int j = j0 + h * 32 + tx * 4;
            const float2 lo = unpk(acc2[i][h][0]);
            const float2 hi = unpk(acc2[i][h][1]);
            *(float4*)(&out[(size_t)r * M + j]) = make_float4(lo.x, lo.y, hi.x, hi.y);
        }
    }
}

// ---------------- fused LSTM step: h-gates GEMM + gx gather + cell ----------
// gates = gx[nbr] + bih + h_{t-1} @ Whh^T + bhh ; K = H only (x-half hoisted).
// Block 64 rows x 32 cells (128 gate cols), 128 threads, f32x2 4x(4x4).
template <int H, int LAYER>
__global__ __launch_bounds__(128, 3)
void lstm_step_k(const int*   __restrict__ nbr_idx,
                 const float* __restrict__ Whh,  // [4H, H]
                 const float* __restrict__ bih,
                 const float* __restrict__ bhh,
                 int t, int n)
{
    const int Kt = d_Kt[t];
    const int r0 = blockIdx.x * 64;
    if (r0 >= Kt) return;
    const int j0 = blockIdx.y * 32;

    constexpr int NCH = H / 16;

    __shared__ __align__(16) float As[2][16][64];
    __shared__ __align__(16) float Ws[2][16][128];

    const float* gx     = (LAYER == 1) ? d_gx1 : d_gx2;
    const float* hread  = (LAYER == 1) ? d_h1[t & 1] : d_h2[t & 1];
    float*       hwrite = (LAYER == 1) ? d_h1[(t + 1) & 1] : d_h2[(t + 1) & 1];
    float*       cst    = (LAYER == 1) ? d_c1 : d_c2;

    const int tid = threadIdx.x;
    const int ty = tid >> 3;  // rows ty*4..+3
    const int tx = tid & 7;   // cell cols tx*4..+3

    ull acc2[4][4][2];
#pragma unroll
    for (int i = 0; i < 4; i++)
#pragma unroll
        for (int q = 0; q < 4; q++) { acc2[i][q][0] = 0ull; acc2[i][q][1] = 0ull; }

    if (t > 0) {  // h_0 == 0 -> Whh half vanishes at t==0
        const int la_row = tid & 63;
        const int la_seg = tid >> 6;
        int ar = r0 + la_row; if (ar > n - 1) ar = n - 1;
        const float* hptr = hread + (size_t)ar * H;

        const int qg = tid >> 5;           // gate group 0..3
        const int jj = j0 + (tid & 31);    // cell column
        const float* wp = Whh + (size_t)(qg * H + jj) * H;

        float4 na0, na1, nw0, nw1, nw2, nw3;
        {
            const int kk = la_seg * 8;
            na0 = *(const float4*)(hptr + kk);
            na1 = *(const float4*)(hptr + kk + 4);
            nw0 = *(const float4*)(wp);
            nw1 = *(const float4*)(wp + 4);
            nw2 = *(const float4*)(wp + 8);
            nw3 = *(const float4*)(wp + 12);
            As[0][kk + 0][la_row] = na0.x; As[0][kk + 1][la_row] = na0.y;
            As[0][kk + 2][la_row] = na0.z; As[0][kk + 3][la_row] = na0.w;
            As[0][kk + 4][la_row] = na1.x; As[0][kk + 5][la_row] = na1.y;
            As[0][kk + 6][la_row] = na1.z; As[0][kk + 7][la_row] = na1.w;
            Ws[0][0][tid] = nw0.x;  Ws[0][1][tid] = nw0.y;  Ws[0][2][tid] = nw0.z;  Ws[0][3][tid] = nw0.w;
            Ws[0][4][tid] = nw1.x;  Ws[0][5][tid] = nw1.y;  Ws[0][6][tid] = nw1.z;  Ws[0][7][tid] = nw1.w;
            Ws[0][8][tid] = nw2.x;  Ws[0][9][tid] = nw2.y;  Ws[0][10][tid] = nw2.z; Ws[0][11][tid] = nw2.w;
            Ws[0][12][tid] = nw3.x; Ws[0][13][tid] = nw3.y; Ws[0][14][tid] = nw3.z; Ws[0][15][tid] = nw3.w;
        }

#pragma unroll 1
        for (int c = 0; c < NCH; c++) {
            __syncthreads();
            const int buf = c & 1;
            const bool more = (c + 1 < NCH);
            if (more) {
                const int kk = (c + 1) * 16;
                na0 = *(const float4*)(hptr + kk + la_seg * 8);
                na1 = *(const float4*)(hptr + kk + la_seg * 8 + 4);
                nw0 = *(const float4*)(wp + kk);
                nw1 = *(const float4*)(wp + kk + 4);
                nw2 = *(const float4*)(wp + kk + 8);
                nw3 = *(const float4*)(wp + kk + 12);
            }
#pragma unroll
            for (int k = 0; k < 16; k++) {
                const float4 av = *(const float4*)(&As[buf][k][ty * 4]);
                ull a2[4];
                a2[0] = bcast2(av.x); a2[1] = bcast2(av.y);
                a2[2] = bcast2(av.z); a2[3] = bcast2(av.w);
                const ulonglong2 w0 = *(const ulonglong2*)(&Ws[buf][k][tx * 4]);
                const ulonglong2 w1 = *(const ulonglong2*)(&Ws[buf][k][32 + tx * 4]);
                const ulonglong2 w2 = *(const ulonglong2*)(&Ws[buf][k][64 + tx * 4]);
                const ulonglong2 w3 = *(const ulonglong2*)(&Ws[buf][k][96 + tx * 4]);
#pragma unroll
                for (int i = 0; i < 4; i++) {
                    fma2(acc2[i][0][0], a2[i], w0.x); fma2(acc2[i][0][1], a2[i], w0.y);
                    fma2(acc2[i][1][0], a2[i], w1.x); fma2(acc2[i][1][1], a2[i], w1.y);
                    fma2(acc2[i][2][0], a2[i], w2.x); fma2(acc2[i][2][1], a2[i], w2.y);
                    fma2(acc2[i][3][0], a2[i], w3.x); fma2(acc2[i][3][1], a2[i], w3.y);
                }
            }
            if (more) {
                const int nb = (c + 1) & 1;
                const int kb = la_seg * 8;
                As[nb][kb + 0][la_row] = na0.x; As[nb][kb + 1][la_row] = na0.y;
                As[nb][kb + 2][la_row] = na0.z; As[nb][kb + 3][la_row] = na0.w;
                As[nb][kb + 4][la_row] = na1.x; As[nb][kb + 5][la_row] = na1.y;
                As[nb][kb + 6][la_row] = na1.z; As[nb][kb + 7][la_row] = na1.w;
                Ws[nb][0][tid] = nw0.x;  Ws[nb][1][tid] = nw0.y;  Ws[nb][2][tid] = nw0.z;  Ws[nb][3][tid] = nw0.w;
                Ws[nb][4][tid] = nw1.x;  Ws[nb][5][tid] = nw1.y;  Ws[nb][6][tid] = nw1.z;  Ws[nb][7][tid] = nw1.w;
                Ws[nb][8][tid] = nw2.x;  Ws[nb][9][tid] = nw2.y;  Ws[nb][10][tid] = nw2.z; Ws[nb][11][tid] = nw2.w;
                Ws[nb][12][tid] = nw3.x; Ws[nb][13][tid] = nw3.y; Ws[nb][14][tid] = nw3.z; Ws[nb][15][tid] = nw3.w;
            }
        }
    }

    // ---- fused LSTM cell epilogue (adds gathered gx + biases) ----
    float bsum[4][4];
#pragma unroll
    for (int cc = 0; cc < 4; cc++) {
        const int j = j0 + tx * 4 + cc;
#pragma unroll
        for (int q = 0; q < 4; q++)
            bsum[q][cc] = bih[q * H + j] + bhh[q * H + j];
    }
#pragma unroll
    for (int i = 0; i < 4; i++) {
        const int r = r0 + ty * 4 + i;
        if (r >= Kt) continue;
        const int node = d_perm[r];
        const int nbr  = nbr_idx[node * DMAXN + t];
        const float* gb = gx + (size_t)nbr * (4 * H) + j0 + tx * 4;
        const float4 g0 = *(const float4*)(gb);
        const float4 g1 = *(const float4*)(gb + H);
        const float4 g2 = *(const float4*)(gb + 2 * H);
        const float4 g3 = *(const float4*)(gb + 3 * H);
        const float gv[4][4] = {{g0.x, g0.y, g0.z, g0.w},
                                {g1.x, g1.y, g1.z, g1.w},
                                {g2.x, g2.y, g2.z, g2.w},
                                {g3.x, g3.y, g3.z, g3.w}};
        float av[4][4];
#pragma unroll
        for (int q = 0; q < 4; q++) {
            const float2 lo = unpk(acc2[i][q][0]);
            const float2 hi = unpk(acc2[i][q][1]);
            av[q][0] = lo.x; av[q][1] = lo.y; av[q][2] = hi.x; av[q][3] = hi.y;
        }
#pragma unroll
        for (int cc = 0; cc < 4; cc++) {
            const int j = j0 + tx * 4 + cc;
            const float gi = av[0][cc] + gv[0][cc] + bsum[0][cc];
            const float gf = av[1][cc] + gv[1][cc] + bsum[1][cc];
            const float gg = av[2][cc] + gv[2][cc] + bsum[2][cc];
            const float go = av[3][cc] + gv[3][cc] + bsum[3][cc];
            const float si = sigmoid_f(gi);
            const float sf = sigmoid_f(gf);
            const float so = sigmoid_f(go);
            const float tg = tanh_f(gg);
            const size_t off = (size_t)r * H + j;
            const float cn = sf * cst[off] + si * tg;
            const float hn = so * tanh_f(cn);
            cst[off] = cn;
            hwrite[off] = hn;
        }
    }
}

// ---------------- fused FC: out = act(A1 @ W1^T + m @ W2^T + b) --------------
template <int K1, int K2, int NOUT, int LAYER>
__global__ __launch_bounds__(128, 4)
void fc_k(const float* __restrict__ A1in,
          const int*   __restrict__ deg,
          const float* __restrict__ W1,  // [NOUT, K1]
          const float* __restrict__ W2,  // [NOUT, K2]
          const float* __restrict__ bias,
          float* __restrict__ outp,
          int n)
{
    const int r0 = blockIdx.x * 64;
    if (r0 >= n) return;
    const int j0 = blockIdx.y * 64;
    constexpr int NCH = (K1 + K2) / 16;

    __shared__ __align__(16) float As[2][16][64];
    __shared__ __align__(16) float Ws[2][16][64];

    const float* A1 = (LAYER == 1) ? A1in : d_hout;
    float* out      = (LAYER == 1) ? d_hout : outp;

    const int tid = threadIdx.x;
    const int la_row = tid & 63;
    const int la_seg = tid >> 6;

    int ar = r0 + la_row; if (ar > n - 1) ar = n - 1;
    const int rk  = d_rank[ar];
    const int par = deg[ar] & 1;
    const float* hbuf = (LAYER == 1) ? d_h1[par] : d_h2[par];
    const float* p1 = A1 + (size_t)ar * K1;
    const float* p2 = hbuf + (size_t)rk * K2;
    const float* q1 = W1 + (size_t)(j0 + la_row) * K1;
    const float* q2 = W2 + (size_t)(j0 + la_row) * K2;

    const int ty = tid >> 3, tx = tid & 7;

    ull acc2[4][2][2];
#pragma unroll
    for (int i = 0; i < 4; i++)
#pragma unroll
        for (int h = 0; h < 2; h++) { acc2[i][h][0] = 0ull; acc2[i][h][1] = 0ull; }

    float4 na0, na1, nw0, nw1;
    {
        const int kk = la_seg * 8;  // < K1 always
        na0 = *(const float4*)(p1 + kk);
        na1 = *(const float4*)(p1 + kk + 4);
        nw0 = *(const float4*)(q1 + kk);
        nw1 = *(const float4*)(q1 + kk + 4);
        As[0][kk + 0][la_row] = na0.x; As[0][kk + 1][la_row] = na0.y;
        As[0][kk + 2][la_row] = na0.z; As[0][kk + 3][la_row] = na0.w;
        As[0][kk + 4][la_row] = na1.x; As[0][kk + 5][la_row] = na1.y;
        As[0][kk + 6][la_row] = na1.z; As[0][kk + 7][la_row] = na1.w;
        Ws[0][kk + 0][la_row] = nw0.x; Ws[0][kk + 1][la_row] = nw0.y;
        Ws[0][kk + 2][la_row] = nw0.z; Ws[0][kk + 3][la_row] = nw0.w;
        Ws[0][kk + 4][la_row] = nw1.x; Ws[0][kk + 5][la_row] = nw1.y;
        Ws[0][kk + 6][la_row] = nw1.z; Ws[0][kk + 7][la_row] = nw1.w;
    }

#pragma unroll 1
    for (int c = 0; c < NCH; c++) {
        __syncthreads();
        const int buf = c & 1;
        const bool more = (c + 1 < NCH);
        if (more) {
            const int kk = (c + 1) * 16 + la_seg * 8;
            const float* pa = (kk < K1) ? (p1 + kk) : (p2 + (kk - K1));
            na0 = *(const float4*)(pa);
            na1 = *(const float4*)(pa + 4);
            const float* pw = (kk < K1) ? (q1 + kk) : (q2 + (kk - K1));
            nw0 = *(const float4*)(pw);
            nw1 = *(const float4*)(pw + 4);
        }
#pragma unroll
        for (int k = 0; k < 16; k++) {
            const float4 av = *(const float4*)(&As[buf][k][ty * 4]);
            ull a2[4];
            a2[0] = bcast2(av.x); a2[1] = bcast2(av.y);
            a2[2] = bcast2(av.z); a2[3] = bcast2(av.w);
            const ulonglong2 w0 = *(const ulonglong2*)(&Ws[buf][k][tx * 4]);
            const ulonglong2 w1 = *(const ulonglong2*)(&Ws[buf][k][32 + tx * 4]);
#pragma unroll
            for (int i = 0; i < 4; i++) {
                fma2(acc2[i][0][0], a2[i], w0.x); fma2(acc2[i][0][1], a2[i], w0.y);
                fma2(acc2[i][1][0], a2[i], w1.x); fma2(acc2[i][1][1], a2[i], w1.y);
            }
        }
        if (more) {
            const int nb = (c + 1) & 1;
            const int kb = la_seg * 8;
            As[nb][kb + 0][la_row] = na0.x; As[nb][kb + 1][la_row] = na0.y;
            As[nb][kb + 2][la_row] = na0.z; As[nb][kb + 3][la_row] = na0.w;
            As[nb][kb + 4][la_row] = na1.x; As[nb][kb + 5][la_row] = na1.y;
            As[nb][kb + 6][la_row] = na1.z; As[nb][kb + 7][la_row] = na1.w;
            Ws[nb][kb + 0][la_row] = nw0.x; Ws[nb][kb + 1][la_row] = nw0.y;
            Ws[nb][kb + 2][la_row] = nw0.z; Ws[nb][kb + 3][la_row] = nw0.w;
            Ws[nb][kb + 4][la_row] = nw1.x; Ws[nb][kb + 5][la_row] = nw1.y;
            Ws[nb][kb + 6][la_row] = nw1.z; Ws[nb][kb + 7][la_row] = nw1.w;
        }
    }

#pragma unroll
    for (int i = 0; i < 4; i++) {
        const int r = r0 + ty * 4 + i;
        if (r >= n) continue;
#pragma unroll
        for (int h = 0; h < 2; h++) {
            const int j = j0 + h * 32 + tx * 4;
            const float2 lo = unpk(acc2[i][h][0]);
            const float2 hi = unpk(acc2[i][h][1]);
            float4 v = make_float4(lo.x + bias[j], lo.y + bias[j + 1],
                                   hi.x + bias[j + 2], hi.y + bias[j + 3]);
            if (LAYER == 1) {
                v.x = fmaxf(v.x, 0.f); v.y = fmaxf(v.y, 0.f);
                v.z = fmaxf(v.z, 0.f); v.w = fmaxf(v.w, 0.f);
            }
            *(float4*)(&out[(size_t)r * NOUT + j]) = v;
        }
    }
}

// ---------------- launch ----------------------------------------------------
extern "C" void kernel_launch(void* const* d_in, const int* in_sizes, int n_in,
                              void* d_out, int out_size)
{
    const float* feat    = (const float*)d_in[0];
    const int*   nbr     = (const int*)d_in[1];
    const int*   deg     = (const int*)d_in[2];
    const float* Wih1    = (const float*)d_in[3];
    const float* Whh1    = (const float*)d_in[4];
    const float* bih1    = (const float*)d_in[5];
    const float* bhh1    = (const float*)d_in[6];
    const float* Wself1  = (const float*)d_in[7];
    const float* Wneigh1 = (const float*)d_in[8];
    const float* b1      = (const float*)d_in[9];
    const float* Wih2    = (const float*)d_in[10];
    const float* Whh2    = (const float*)d_in[11];
    const float* bih2    = (const float*)d_in[12];
    const float* bhh2    = (const float*)d_in[13];
    const float* Wself2  = (const float*)d_in[14];
    const float* Wneigh2 = (const float*)d_in[15];
    const float* b2      = (const float*)d_in[16];

    const int n  = in_sizes[2];          // = N
    const int rb = (n + 63) / 64;

    // degree sort (descending) + K_t table
    sort_zero_k<<<1, 32>>>();
    sort_hist_k<<<(n + 255) / 256, 256>>>(deg, n);
    sort_scan_k<<<1, 1>>>();
    sort_scatter_k<<<(n + 255) / 256, 256>>>(deg, n);

    // zero cell states (h never read before written)
    zero_states_k<<<4096, 256>>>();

    // precompute layer-1 x-gates: gx1 = feat @ Wih1^T  [N, 512]
    gemm_xw_k<128, 1><<<dim3(rb, 8), 128>>>(feat, Wih1, n);

    // layer 1 LSTM (h-half only), 16 steps
    for (int t = 0; t < 16; t++)
        lstm_step_k<128, 1><<<dim3(rb, 4), 128>>>(nbr, Whh1, bih1, bhh1, t, n);

    // layer 1 FC + relu -> d_hout [N, 256]
    fc_k<128, 128, 256, 1><<<dim3(rb, 4), 128>>>(feat, deg, Wself1, Wneigh1,
                                                 b1, nullptr, n);

    // precompute layer-2 x-gates: gx2 = hout @ Wih2^T  [N, 1024]
    gemm_xw_k<256, 2><<<dim3(rb, 16), 128>>>(nullptr, Wih2, n);

    // layer 2 LSTM (h-half only), 16 steps
    for (int t = 0; t < 16; t++)
        lstm_step_k<256, 2><<<dim3(rb, 8), 128>>>(nbr, Whh2, bih2, bhh2, t, n);

    // layer 2 FC -> d_out [N, 64]
    fc_k<256, 256, 64, 2><<<dim3(rb, 1), 128>>>(feat, deg, Wself2, Wneigh2,
                                                b2, (float*)d_out, n);
}

// round 7
// speedup vs baseline: 4.8296x; 2.3210x over previous
#include <cuda_runtime.h>
#include <math.h>
#include <stdint.h>

#define NN    30000
#define DMAXN 16
#define INF   128
#define HIDF  256

typedef uint32_t u32;

// ---------------- tf32 mma helpers ------------------------------------------
__device__ __forceinline__ u32 f2tf(float x) {
    u32 r; asm("cvt.rna.tf32.f32 %0, %1;" : "=r"(r) : "f"(x)); return r;
}
__device__ __forceinline__ uint4 cvt4(float4 v) {
    return make_uint4(f2tf(v.x), f2tf(v.y), f2tf(v.z), f2tf(v.w));
}
// D(16x8) += A(16x8,row) * B(8x8,col);  a:4 regs, b:2 regs, d:4 fp32
__device__ __forceinline__ void mma8(float* d, const u32* a, const u32* b) {
    asm volatile("mma.sync.aligned.m16n8k8.row.col.f32.tf32.tf32.f32 "
                 "{%0,%1,%2,%3}, {%4,%5,%6,%7}, {%8,%9}, {%0,%1,%2,%3};"
                 : "+f"(d[0]), "+f"(d[1]), "+f"(d[2]), "+f"(d[3])
                 : "r"(a[0]), "r"(a[1]), "r"(a[2]), "r"(a[3]),
                   "r"(b[0]), "r"(b[1]));
}

__device__ __forceinline__ float sigmoid_f(float x) {
    return __fdividef(1.f, 1.f + __expf(-x));
}
__device__ __forceinline__ float tanh_f(float x) {
    float ax = fabsf(x);
    float e = __expf(-2.f * ax);
    return copysignf(__fdividef(1.f - e, 1.f + e), x);
}

// ---------------- scratch (device globals) -----------------------------------
__device__ float d_h1[2][NN * INF];
__device__ float d_c1[NN * INF];
__device__ float d_hout[NN * HIDF];
__device__ float d_h2[2][NN * HIDF];
__device__ float d_c2[NN * HIDF];
__device__ float d_gx1[NN * 4 * INF];
__device__ float d_gx2[NN * 4 * HIDF];
__device__ int   d_perm[NN];
__device__ int   d_rank[NN];
__device__ int   d_cnt[DMAXN + 2];
__device__ int   d_ofs[DMAXN + 2];
__device__ int   d_Kt[DMAXN + 1];

// ---------------- counting sort by degree (descending) ----------------------
__global__ void sort_zero_k() {
    if (threadIdx.x < DMAXN + 2) d_cnt[threadIdx.x] = 0;
}
__global__ void sort_hist_k(const int* __restrict__ deg, int n) {
    int i = blockIdx.x * blockDim.x + threadIdx.x;
    if (i < n) atomicAdd(&d_cnt[deg[i]], 1);
}
__global__ void sort_scan_k() {
    int ofs[DMAXN + 2];
    int run = 0;
    for (int d = DMAXN; d >= 1; --d) { ofs[d] = run; run += d_cnt[d]; }
    for (int d = 1; d <= DMAXN; ++d) d_ofs[d] = ofs[d];
    for (int t = 0; t < DMAXN; ++t) d_Kt[t] = ofs[t + 1] + d_cnt[t + 1];
}
__global__ void sort_scatter_k(const int* __restrict__ deg, int n) {
    int i = blockIdx.x * blockDim.x + threadIdx.x;
    if (i < n) {
        int p = atomicAdd(&d_ofs[deg[i]], 1);
        d_perm[p] = i;
        d_rank[i] = p;
    }
}

__global__ void zero_states_k() {
    const int n1 = NN * INF / 4;
    const int n2 = NN * HIDF / 4;
    float4 z = make_float4(0.f, 0.f, 0.f, 0.f);
    int stride = gridDim.x * blockDim.x;
    for (int i = blockIdx.x * blockDim.x + threadIdx.x; i < n2; i += stride) {
        reinterpret_cast<float4*>(d_c2)[i] = z;
        if (i < n1) reinterpret_cast<float4*>(d_c1)[i] = z;
    }
}

// ============================================================================
// gx = A @ W^T : A [n,K] fp32, W [4K,K] row-major, out [n,4K]
// Block tile 128x128, 8 warps, warp = M16 x N128. Kc=16, stride-20 smem pad.
// ============================================================================
template <int K, int SRC>
__global__ __launch_bounds__(256, 2)
void mma_gx_k(const float* __restrict__ Ain, const float* __restrict__ W, int n)
{
    const int r0 = blockIdx.x * 128;
    if (r0 >= n) return;
    const int n0 = blockIdx.y * 128;
    constexpr int NCH = K / 16;
    constexpr int M4 = 4 * K;

    __shared__ u32 As[2][128][20];
    __shared__ u32 Bs[2][128][20];

    const float* A = (SRC == 1) ? Ain : d_hout;
    float* out     = (SRC == 1) ? d_gx1 : d_gx2;

    const int tid = threadIdx.x;
    const int w = tid >> 5, lane = tid & 31;
    const int q = lane >> 2, tig = lane & 3;

    const int prow = tid >> 2;
    const int c4   = (tid & 3) * 4;
    int ra0 = r0 + prow;      if (ra0 > n - 1) ra0 = n - 1;
    int ra1 = r0 + prow + 64; if (ra1 > n - 1) ra1 = n - 1;
    const float* pa0 = A + (size_t)ra0 * K;
    const float* pa1 = A + (size_t)ra1 * K;
    const float* pb0 = W + (size_t)(n0 + prow) * K;
    const float* pb1 = W + (size_t)(n0 + prow + 64) * K;

    float acc[16][4];
#pragma unroll
    for (int i = 0; i < 16; i++)
#pragma unroll
        for (int c = 0; c < 4; c++) acc[i][c] = 0.f;

    float4 fa0 = *(const float4*)(pa0 + c4);
    float4 fa1 = *(const float4*)(pa1 + c4);
    float4 fb0 = *(const float4*)(pb0 + c4);
    float4 fb1 = *(const float4*)(pb1 + c4);
    *(uint4*)&As[0][prow][c4]      = cvt4(fa0);
    *(uint4*)&As[0][prow + 64][c4] = cvt4(fa1);
    *(uint4*)&Bs[0][prow][c4]      = cvt4(fb0);
    *(uint4*)&Bs[0][prow + 64][c4] = cvt4(fb1);

#pragma unroll 1
    for (int cch = 0; cch < NCH; cch++) {
        __syncthreads();
        const int buf = cch & 1;
        const bool more = (cch + 1 < NCH);
        if (more) {
            const int kg = (cch + 1) * 16 + c4;
            fa0 = *(const float4*)(pa0 + kg);
            fa1 = *(const float4*)(pa1 + kg);
            fb0 = *(const float4*)(pb0 + kg);
            fb1 = *(const float4*)(pb1 + kg);
        }
#pragma unroll
        for (int kk = 0; kk < 16; kk += 8) {
            u32 afr[4];
            afr[0] = As[buf][w * 16 + q][kk + tig];
            afr[1] = As[buf][w * 16 + q + 8][kk + tig];
            afr[2] = As[buf][w * 16 + q][kk + tig + 4];
            afr[3] = As[buf][w * 16 + q + 8][kk + tig + 4];
#pragma unroll
            for (int nf = 0; nf < 16; nf++) {
                u32 bfr[2];
                bfr[0] = Bs[buf][nf * 8 + q][kk + tig];
                bfr[1] = Bs[buf][nf * 8 + q][kk + tig + 4];
                mma8(acc[nf], afr, bfr);
            }
        }
        if (more) {
            const int nb = (cch + 1) & 1;
            *(uint4*)&As[nb][prow][c4]      = cvt4(fa0);
            *(uint4*)&As[nb][prow + 64][c4] = cvt4(fa1);
            *(uint4*)&Bs[nb][prow][c4]      = cvt4(fb0);
            *(uint4*)&Bs[nb][prow + 64][c4] = cvt4(fb1);
        }
    }

#pragma unroll
    for (int mrow = 0; mrow < 2; mrow++) {
        const int r = r0 + w * 16 + q + mrow * 8;
        if (r >= n) continue;
        float* op = out + (size_t)r * M4 + n0 + 2 * tig;
#pragma unroll
        for (int nf = 0; nf < 16; nf++)
            *(float2*)(op + nf * 8) =
                make_float2(acc[nf][mrow * 2], acc[nf][mrow * 2 + 1]);
    }
}

// ============================================================================
// Fused LSTM step (tensor): gates = h_{t-1} @ Whh^T (+ gathered gx + biases)
// Block: 128 rows x (4 gates x 32 cells). Warp = M16 x N128: each thread holds
// all 4 gates of its cells -> fused cell update in registers.
// ============================================================================
template <int H, int LAYER>
__global__ __launch_bounds__(256, 2)
void mma_lstm_k(const int*   __restrict__ nbr_idx,
                const float* __restrict__ Whh,   // [4H, H]
                const float* __restrict__ bih,
                const float* __restrict__ bhh,
                int t, int n)
{
    const int Kt = d_Kt[t];
    const int r0 = blockIdx.x * 128;
    if (r0 >= Kt) return;
    const int j0 = blockIdx.y * 32;
    constexpr int NCH = H / 16;

    __shared__ u32 As[2][128][20];
    __shared__ u32 Bs[2][128][20];
    __shared__ int s_nbr[128];

    const float* gx     = (LAYER == 1) ? d_gx1 : d_gx2;
    const float* hread  = (LAYER == 1) ? d_h1[t & 1] : d_h2[t & 1];
    float*       hwrite = (LAYER == 1) ? d_h1[(t + 1) & 1] : d_h2[(t + 1) & 1];
    float*       cst    = (LAYER == 1) ? d_c1 : d_c2;

    const int tid = threadIdx.x;
    const int w = tid >> 5, lane = tid & 31;
    const int q = lane >> 2, tig = lane & 3;

    float acc[16][4];
#pragma unroll
    for (int i = 0; i < 16; i++)
#pragma unroll
        for (int c = 0; c < 4; c++) acc[i][c] = 0.f;

    if (t > 0) {   // h_0 == 0 -> GEMM vanishes at t==0
        const int prow = tid >> 2;
        const int c4   = (tid & 3) * 4;
        int ra0 = r0 + prow;      if (ra0 > n - 1) ra0 = n - 1;
        int ra1 = r0 + prow + 64; if (ra1 > n - 1) ra1 = n - 1;
        const float* pa0 = hread + (size_t)ra0 * H;
        const float* pa1 = hread + (size_t)ra1 * H;
        // gate-grouped B rows: brow -> W row (brow>>5)*H + j0 + (brow&31)
        const float* pb0 = Whh + (size_t)((prow >> 5) * H + j0 + (prow & 31)) * H;
        const float* pb1 = Whh + (size_t)((((prow + 64) >> 5)) * H + j0 + ((prow + 64) & 31)) * H;

        float4 fa0 = *(const float4*)(pa0 + c4);
        float4 fa1 = *(const float4*)(pa1 + c4);
        float4 fb0 = *(const float4*)(pb0 + c4);
        float4 fb1 = *(const float4*)(pb1 + c4);
        *(uint4*)&As[0][prow][c4]      = cvt4(fa0);
        *(uint4*)&As[0][prow + 64][c4] = cvt4(fa1);
        *(uint4*)&Bs[0][prow][c4]      = cvt4(fb0);
        *(uint4*)&Bs[0][prow + 64][c4] = cvt4(fb1);

#pragma unroll 1
        for (int cch = 0; cch < NCH; cch++) {
            __syncthreads();
            const int buf = cch & 1;
            const bool more = (cch + 1 < NCH);
            if (more) {
                const int kg = (cch + 1) * 16 + c4;
                fa0 = *(const float4*)(pa0 + kg);
                fa1 = *(const float4*)(pa1 + kg);
                fb0 = *(const float4*)(pb0 + kg);
                fb1 = *(const float4*)(pb1 + kg);
            }
#pragma unroll
            for (int kk = 0; kk < 16; kk += 8) {
                u32 afr[4];
                afr[0] = As[buf][w * 16 + q][kk + tig];
                afr[1] = As[buf][w * 16 + q + 8][kk + tig];
                afr[2] = As[buf][w * 16 + q][kk + tig + 4];
                afr[3] = As[buf][w * 16 + q + 8][kk + tig + 4];
#pragma unroll
                for (int nf = 0; nf < 16; nf++) {
                    u32 bfr[2];
                    bfr[0] = Bs[buf][nf * 8 + q][kk + tig];
                    bfr[1] = Bs[buf][nf * 8 + q][kk + tig + 4];
                    mma8(acc[nf], afr, bfr);
                }
            }
            if (more) {
                const int nb = (cch + 1) & 1;
                *(uint4*)&As[nb][prow][c4]      = cvt4(fa0);
                *(uint4*)&As[nb][prow + 64][c4] = cvt4(fa1);
                *(uint4*)&Bs[nb][prow][c4]      = cvt4(fb0);
                *(uint4*)&Bs[nb][prow + 64][c4] = cvt4(fb1);
            }
        }
    }

    __syncthreads();
    if (tid < 128) {
        int r = r0 + tid; if (r > Kt - 1) r = Kt - 1;
        s_nbr[tid] = nbr_idx[d_perm[r] * DMAXN + t];
    }
    __syncthreads();

    float2 bsum[4][4];
#pragma unroll
    for (int g = 0; g < 4; g++)
#pragma unroll
        for (int cg = 0; cg < 4; cg++) {
            const int j = j0 + cg * 8 + 2 * tig;
            const float2 bv1 = *(const float2*)(bih + g * H + j);
            const float2 bv2 = *(const float2*)(bhh + g * H + j);
            bsum[g][cg] = make_float2(bv1.x + bv2.x, bv1.y + bv2.y);
        }

#pragma unroll
    for (int mrow = 0; mrow < 2; mrow++) {
        const int lr = w * 16 + q + mrow * 8;
        const int r = r0 + lr;
        if (r >= Kt) continue;
        const int nbr = s_nbr[lr];
        const float* gb = gx + (size_t)nbr * (4 * H) + j0 + 2 * tig;
#pragma unroll
        for (int cg = 0; cg < 4; cg++) {
            const int j = j0 + cg * 8 + 2 * tig;
            const float2 g0 = *(const float2*)(gb + cg * 8);
            const float2 g1 = *(const float2*)(gb + cg * 8 + H);
            const float2 g2 = *(const float2*)(gb + cg * 8 + 2 * H);
            const float2 g3 = *(const float2*)(gb + cg * 8 + 3 * H);
            const float2 cold = *(const float2*)(cst + (size_t)r * H + j);
            float cn[2], hn[2];
#pragma unroll
            for (int c = 0; c < 2; c++) {
                const float gi = acc[0 + cg][mrow * 2 + c]  + (c ? g0.y : g0.x) + (c ? bsum[0][cg].y : bsum[0][cg].x);
                const float gf = acc[4 + cg][mrow * 2 + c]  + (c ? g1.y : g1.x) + (c ? bsum[1][cg].y : bsum[1][cg].x);
                const float gg = acc[8 + cg][mrow * 2 + c]  + (c ? g2.y : g2.x) + (c ? bsum[2][cg].y : bsum[2][cg].x);
                const float go = acc[12 + cg][mrow * 2 + c] + (c ? g3.y : g3.x) + (c ? bsum[3][cg].y : bsum[3][cg].x);
                const float cv = sigmoid_f(gf) * (c ? cold.y : cold.x)
                               + sigmoid_f(gi) * tanh_f(gg);
                cn[c] = cv;
                hn[c] = sigmoid_f(go) * tanh_f(cv);
            }
            *(float2*)(cst + (size_t)r * H + j)    = make_float2(cn[0], cn[1]);
            *(float2*)(hwrite + (size_t)r * H + j) = make_float2(hn[0], hn[1]);
        }
    }
}

// ============================================================================
// Fused FC (tensor): out = act(A1 @ W1^T + m @ W2^T + b), K = K1+K2 concat.
// ============================================================================
template <int K1, int K2, int NOUT, int BLKN, int LAYER>
__global__ __launch_bounds__(256, 2)
void mma_fc_k(const float* __restrict__ A1in, const int* __restrict__ deg,
              const float* __restrict__ W1, const float* __restrict__ W2,
              const float* __restrict__ bias, float* __restrict__ outp, int n)
{
    const int r0 = blockIdx.x * 128;
    if (r0 >= n) return;
    const int n0 = blockIdx.y * BLKN;
    constexpr int NCH = (K1 + K2) / 16;
    constexpr int NFR = BLKN / 8;

    __shared__ u32 As[2][128][20];
    __shared__ u32 Bs[2][BLKN][20];

    const float* A1 = (LAYER == 1) ? A1in : d_hout;
    float* out      = (LAYER == 1) ? d_hout : outp;

    const int tid = threadIdx.x;
    const int w = tid >> 5, lane = tid & 31;
    const int q = lane >> 2, tig = lane & 3;

    const int prow = tid >> 2;
    const int c4   = (tid & 3) * 4;

    int ra0 = r0 + prow;      if (ra0 > n - 1) ra0 = n - 1;
    int ra1 = r0 + prow + 64; if (ra1 > n - 1) ra1 = n - 1;
    const float* p1a = A1 + (size_t)ra0 * K1;
    const float* p1b = A1 + (size_t)ra1 * K1;
    const float* h0a = (LAYER == 1) ? d_h1[deg[ra0] & 1] : d_h2[deg[ra0] & 1];
    const float* h0b = (LAYER == 1) ? d_h1[deg[ra1] & 1] : d_h2[deg[ra1] & 1];
    const float* p2a = h0a + (size_t)d_rank[ra0] * K2;
    const float* p2b = h0b + (size_t)d_rank[ra1] * K2;
    const float* q1a = W1 + (size_t)(n0 + prow) * K1;
    const float* q2a = W2 + (size_t)(n0 + prow) * K2;
    const float* q1b = W1 + (size_t)(n0 + (prow & (BLKN - 1 - 64)) + 64) * K1; // only used if BLKN==128
    const float* q2b = W2 + (size_t)(n0 + (prow & 63) + 64) * K2;

    float acc[NFR][4];
#pragma unroll
    for (int i = 0; i < NFR; i++)
#pragma unroll
        for (int c = 0; c < 4; c++) acc[i][c] = 0.f;

    auto ldA = [&](const float* pk1, const float* pk2, int kg) {
        return (kg < K1) ? *(const float4*)(pk1 + kg)
                         : *(const float4*)(pk2 + (kg - K1));
    };

    float4 fa0 = ldA(p1a, p2a, c4);
    float4 fa1 = ldA(p1b, p2b, c4);
    float4 fb0 = ldA(q1a, q2a, c4);
    float4 fb1;
    if (BLKN == 128) fb1 = ldA(q1b, q2b, c4);
    *(uint4*)&As[0][prow][c4]      = cvt4(fa0);
    *(uint4*)&As[0][prow + 64][c4] = cvt4(fa1);
    if (BLKN == 128) {
        *(uint4*)&Bs[0][prow][c4]                  = cvt4(fb0);
        *(uint4*)&Bs[0][(prow & 63) + 64][c4]      = cvt4(fb1);
    } else if (prow < BLKN) {
        *(uint4*)&Bs[0][prow][c4] = cvt4(fb0);
    }

#pragma unroll 1
    for (int cch = 0; cch < NCH; cch++) {
        __syncthreads();
        const int buf = cch & 1;
        const bool more = (cch + 1 < NCH);
        if (more) {
            const int kg = (cch + 1) * 16 + c4;
            fa0 = ldA(p1a, p2a, kg);
            fa1 = ldA(p1b, p2b, kg);
            fb0 = ldA(q1a, q2a, kg);
            if (BLKN == 128) fb1 = ldA(q1b, q2b, kg);
        }
#pragma unroll
        for (int kk = 0; kk < 16; kk += 8) {
            u32 afr[4];
            afr[0] = As[buf][w * 16 + q][kk + tig];
            afr[1] = As[buf][w * 16 + q + 8][kk + tig];
            afr[2] = As[buf][w * 16 + q][kk + tig + 4];
            afr[3] = As[buf][w * 16 + q + 8][kk + tig + 4];
#pragma unroll
            for (int nf = 0; nf < NFR; nf++) {
                u32 bfr[2];
                bfr[0] = Bs[buf][nf * 8 + q][kk + tig];
                bfr[1] = Bs[buf][nf * 8 + q][kk + tig + 4];
                mma8(acc[nf], afr, bfr);
            }
        }
        if (more) {
            const int nb = (cch + 1) & 1;
            *(uint4*)&As[nb][prow][c4]      = cvt4(fa0);
            *(uint4*)&As[nb][prow + 64][c4] = cvt4(fa1);
            if (BLKN == 128) {
                *(uint4*)&Bs[nb][prow][c4]             = cvt4(fb0);
                *(uint4*)&Bs[nb][(prow & 63) + 64][c4] = cvt4(fb1);
            } else if (prow < BLKN) {
                *(uint4*)&Bs[nb][prow][c4] = cvt4(fb0);
            }
        }
    }

#pragma unroll
    for (int mrow = 0; mrow < 2; mrow++) {
        const int r = r0 + w * 16 + q + mrow * 8;
        if (r >= n) continue;
        float* op = out + (size_t)r * NOUT + n0 + 2 * tig;
#pragma unroll
        for (int nf = 0; nf < NFR; nf++) {
            const int nn = n0 + nf * 8 + 2 * tig;
            float v0 = acc[nf][mrow * 2]     + bias[nn];
            float v1 = acc[nf][mrow * 2 + 1] + bias[nn + 1];
            if (LAYER == 1) { v0 = fmaxf(v0, 0.f); v1 = fmaxf(v1, 0.f); }
            *(float2*)(op + nf * 8) = make_float2(v0, v1);
        }
    }
}

// ---------------- launch ----------------------------------------------------
extern "C" void kernel_launch(void* const* d_in, const int* in_sizes, int n_in,
                              void* d_out, int out_size)
{
    const float* feat    = (const float*)d_in[0];
    const int*   nbr     = (const int*)d_in[1];
    const int*   deg     = (const int*)d_in[2];
    const float* Wih1    = (const float*)d_in[3];
    const float* Whh1    = (const float*)d_in[4];
    const float* bih1    = (const float*)d_in[5];
    const float* bhh1    = (const float*)d_in[6];
    const float* Wself1  = (const float*)d_in[7];
    const float* Wneigh1 = (const float*)d_in[8];
    const float* b1      = (const float*)d_in[9];
    const float* Wih2    = (const float*)d_in[10];
    const float* Whh2    = (const float*)d_in[11];
    const float* bih2    = (const float*)d_in[12];
    const float* bhh2    = (const float*)d_in[13];
    const float* Wself2  = (const float*)d_in[14];
    const float* Wneigh2 = (const float*)d_in[15];
    const float* b2      = (const float*)d_in[16];

    const int n  = in_sizes[2];           // = N
    const int rb = (n + 127) / 128;

    sort_zero_k<<<1, 32>>>();
    sort_hist_k<<<(n + 255) / 256, 256>>>(deg, n);
    sort_scan_k<<<1, 1>>>();
    sort_scatter_k<<<(n + 255) / 256, 256>>>(deg, n);

    zero_states_k<<<4096, 256>>>();

    // layer 1: gx1 = feat @ Wih1^T  [N, 512]
    mma_gx_k<128, 1><<<dim3(rb, 4), 256>>>(feat, Wih1, n);
    for (int t = 0; t < 16; t++)
        mma_lstm_k<128, 1><<<dim3(rb, 4), 256>>>(nbr, Whh1, bih1, bhh1, t, n);
    mma_fc_k<128, 128, 256, 128, 1><<<dim3(rb, 2), 256>>>(feat, deg, Wself1,
                                                          Wneigh1, b1, nullptr, n);

    // layer 2: gx2 = hout @ Wih2^T  [N, 1024]
    mma_gx_k<256, 2><<<dim3(rb, 8), 256>>>(nullptr, Wih2, n);
    for (int t = 0; t < 16; t++)
        mma_lstm_k<256, 2><<<dim3(rb, 8), 256>>>(nbr, Whh2, bih2, bhh2, t, n);
    mma_fc_k<256, 256, 64, 64, 2><<<dim3(rb, 1), 256>>>(feat, deg, Wself2,
                                                        Wneigh2, b2,
                                                        (float*)d_out, n);
}